// round 11
// baseline (speedup 1.0000x reference)
#include <cuda_runtime.h>
#include <cuda_bf16.h>
#include <math.h>
#include <stdint.h>

// ---------------------------------------------------------------------------
// Problem constants
// ---------------------------------------------------------------------------
#define N_IMG   8
#define PER_IM  256
#define NPROP   2048
#define CCH     256
#define NPTS    49
#define CIN     12544         // 256*49
#define CMID    1024
#define IMTOP   100
#define SCORE_THR 0.05f
#define IOU_THR   0.5f
#define BBOX_CLAMP 4.135166556742356f

__device__ __constant__ int   c_HS[4]   = {160, 80, 40, 20};
__device__ __constant__ int   c_OFFS[4] = {0, 204800, 256000, 268800};
__device__ __constant__ float c_STR[4]  = {4.f, 8.f, 16.f, 32.f};

#define TOTPX 272000

// ---------------------------------------------------------------------------
// Device scratch
// ---------------------------------------------------------------------------
__device__ __align__(128) float g_pix [TOTPX * CCH];           // NHWC fmaps
__device__ __align__(128) float g_roi [(size_t)NPROP * CIN];   // roi (n, k)
__device__ __align__(128) float g_w6T [(size_t)CIN * CMID];    // fc6_w (k, m)
__device__ __align__(128) float g_w7T [(size_t)CMID * CMID];   // fc7_w (k, m)
__device__ __align__(128) float g_h1 [(size_t)NPROP * CMID];   // h1 (n, k)
__device__ __align__(128) float g_h2 [(size_t)NPROP * CMID];
__device__ float g_scr[NPROP];
__device__ float g_box[NPROP * 4];

// ---------------------------------------------------------------------------
// PTX helpers
// ---------------------------------------------------------------------------
__device__ __forceinline__ uint32_t smem_addr_u32(const void* p) {
    uint32_t a;
    asm("{ .reg .u64 t; cvta.to.shared.u64 t, %1; cvt.u32.u64 %0, t; }"
        : "=r"(a) : "l"(p));
    return a;
}
__device__ __forceinline__ void cpa16(uint32_t saddr, const float* g) {
    asm volatile("cp.async.cg.shared.global [%0], [%1], 16;"
                 :: "r"(saddr), "l"(g));
}

// ---------------------------------------------------------------------------
// Scalar strided transpose (R8 version)
// Y[j*outRS + i] = X[i*inRS + j]
// ---------------------------------------------------------------------------
__global__ void ktranspose_s(const float* __restrict__ in, float* __restrict__ out,
                             int R, int Cc, long long inRS, long long outRS,
                             long long zIn, long long zOut)
{
    __shared__ float tile[32][33];
    const float* X = in  + (long long)blockIdx.z * zIn;
    float*       Y = out + (long long)blockIdx.z * zOut;
    int j0 = blockIdx.x * 32;
    int i0 = blockIdx.y * 32;
    int tx = threadIdx.x, ty = threadIdx.y;
#pragma unroll
    for (int u = 0; u < 32; u += 8) {
        int i = i0 + ty + u, j = j0 + tx;
        if (i < R && j < Cc) tile[ty + u][tx] = X[(long long)i * inRS + j];
    }
    __syncthreads();
#pragma unroll
    for (int u = 0; u < 32; u += 8) {
        int j = j0 + ty + u, i = i0 + tx;
        if (j < Cc && i < R) Y[(long long)j * outRS + i] = tile[tx][ty + u];
    }
}

// ---------------------------------------------------------------------------
// ROI align (R8 version; block per roi, 256 threads = channels)
// ---------------------------------------------------------------------------
__global__ void roi_align_kernel(const float* __restrict__ proposals,
                                 const int* __restrict__ imidx,
                                 const float* __restrict__ pix,
                                 float* __restrict__ roi)
{
    int n = blockIdx.x;
    int c = threadIdx.x;

    __shared__ int   s_idx[NPTS][4];
    __shared__ float s_w[NPTS][4];

    float x1 = proposals[n * 4 + 0];
    float y1 = proposals[n * 4 + 1];
    float x2 = proposals[n * 4 + 2];
    float y2 = proposals[n * 4 + 3];

    float area = fmaxf(x2 - x1, 0.f) * fmaxf(y2 - y1, 0.f);
    float lf = floorf(4.0f + log2f(sqrtf(area) / 224.0f + 1e-8f));
    lf = fminf(fmaxf(lf, 2.0f), 5.0f);
    int lvl = (int)lf - 2;

    int   H  = c_HS[lvl];
    int   W  = H;
    float sc = 1.0f / c_STR[lvl];
    int   b  = imidx[n];
    int   basepx = c_OFFS[lvl] + b * H * W;

    if (threadIdx.x < NPTS) {
        int p = threadIdx.x;
        int i = p / 7, j = p % 7;
        float stepx = (x2 - x1) * sc / 7.0f;
        float stepy = (y2 - y1) * sc / 7.0f;
        float gx = x1 * sc + ((float)j + 0.5f) * stepx;
        float gy = y1 * sc + ((float)i + 0.5f) * stepy;
        float x = fminf(fmaxf(gx, 0.f), (float)W - 1.0f);
        float y = fminf(fmaxf(gy, 0.f), (float)H - 1.0f);
        float x0f = floorf(x), y0f = floorf(y);
        int x0i = (int)x0f, y0i = (int)y0f;
        int x1i = min(x0i + 1, W - 1);
        int y1i = min(y0i + 1, H - 1);
        float fx = x - x0f, fy = y - y0f;
        s_idx[p][0] = basepx + y0i * W + x0i;
        s_idx[p][1] = basepx + y0i * W + x1i;
        s_idx[p][2] = basepx + y1i * W + x0i;
        s_idx[p][3] = basepx + y1i * W + x1i;
        s_w[p][0] = (1.f - fy) * (1.f - fx);
        s_w[p][1] = (1.f - fy) * fx;
        s_w[p][2] = fy * (1.f - fx);
        s_w[p][3] = fy * fx;
    }
    __syncthreads();

    float* out = roi + (size_t)n * CIN;
#pragma unroll 1
    for (int p = 0; p < NPTS; p++) {
        float v = s_w[p][0] * pix[(size_t)s_idx[p][0] * CCH + c]
                + s_w[p][1] * pix[(size_t)s_idx[p][1] * CCH + c]
                + s_w[p][2] * pix[(size_t)s_idx[p][2] * CCH + c]
                + s_w[p][3] * pix[(size_t)s_idx[p][3] * CCH + c];
        out[p * CCH + c] = v;
    }
}

// ---------------------------------------------------------------------------
// Mixed-layout fp32 GEMM, bitwise-identical numerics to R1/R8:
//   per element: single fp32 accumulator, fma.rn over ascending k,
//   then acc + bias, then fmaxf.
// A: (M x K) ROW-major (n-major) — loaded coalesced (LDG.128) and transposed
//    into smem via conflict-free STS (row stride 130, banks (8q+2j+r)%32
//    all distinct, even stride keeps ULL fragment loads 8B-aligned).
// B: (K x Nn) k-major — cp.async, unchanged from R8.
// Schedule/tile identical to R8: 128m x 64n x 16k, 256 thr, 8 warps
// (4m x 2n of 32x32), thread 8m x 4n, double-buffered, 2 CTAs/SM.
// C written row-major (M x Nn).
// ---------------------------------------------------------------------------
#define GM 128
#define GN 64
#define GK 16
#define GMP (GM + 2)          // padded A row stride (even -> 8B-aligned ULL)

__global__ __launch_bounds__(256, 2)
void gemm_an(const float* __restrict__ A, const float* __restrict__ BT,
             const float* __restrict__ bias, float* __restrict__ C,
             int M, int Nn, int K)
{
    __shared__ float As[2][GK][GMP];
    __shared__ float Bs[2][GK][GN];

    const int tid = threadIdx.x;
    const int wid = tid >> 5;
    const int lane = tid & 31;
    const int wm = wid & 3;           // 4 m-slots of 32
    const int wn = wid >> 2;          // 2 n-slots of 32
    const int ty = lane >> 3;         // 4 m-subslots of 8
    const int tx = lane & 7;          // 8 n-subslots of 4
    const int m0 = blockIdx.y * GM;
    const int n0 = blockIdx.x * GN;

    const int ar = tid >> 2;          // A-load row 0..63 (and +64)
    const int aq = tid & 3;           // A-load quad (k = 4*aq..4*aq+3)

    // acc[i][j]: packed fp32 pair = rows (ty*8+2i, +1), col j
    unsigned long long acc[4][4];
#pragma unroll
    for (int i = 0; i < 4; i++)
#pragma unroll
        for (int j = 0; j < 4; j++) acc[i][j] = 0ull;

    const int NCH = K / GK;

    auto issue = [&](int ch, int s) {
        int kc = ch * GK;
        // A: row-major, coalesced LDG.128, transposed STS into As[k][m]
#pragma unroll
        for (int p = 0; p < 2; p++) {
            int r = ar + p * 64;
            float4 v = *(const float4*)(A + (size_t)(m0 + r) * K + kc + aq * 4);
            As[s][aq * 4 + 0][r] = v.x;
            As[s][aq * 4 + 1][r] = v.y;
            As[s][aq * 4 + 2][r] = v.z;
            As[s][aq * 4 + 3][r] = v.w;
        }
        // B: k-major, cp.async (256 float4, 1/thread)
        {
            int kr = tid >> 4, cn = (tid & 15) * 4;
            cpa16(smem_addr_u32(&Bs[s][kr][cn]),
                  BT + (size_t)(kc + kr) * Nn + n0 + cn);
        }
    };

    issue(0, 0);
    asm volatile("cp.async.commit_group;");

    for (int ch = 0; ch < NCH; ch++) {
        int s = ch & 1;
        if (ch + 1 < NCH) {
            issue(ch + 1, s ^ 1);
            asm volatile("cp.async.commit_group;");
            asm volatile("cp.async.wait_group 1;");
        } else {
            asm volatile("cp.async.wait_group 0;");
        }
        __syncthreads();

#pragma unroll
        for (int kk = 0; kk < GK; kk++) {
            const unsigned long long* ap =
                (const unsigned long long*)&As[s][kk][wm * 32 + ty * 8];
            unsigned long long a0 = ap[0], a1 = ap[1], a2 = ap[2], a3 = ap[3];
            const float4 bv = *(const float4*)&Bs[s][kk][wn * 32 + tx * 4];
            const float* b = &bv.x;
#pragma unroll
            for (int j = 0; j < 4; j++) {
                unsigned long long b2;
                asm("mov.b64 %0, {%1, %1};" : "=l"(b2) : "f"(b[j]));
                asm("fma.rn.f32x2 %0, %1, %2, %0;" : "+l"(acc[0][j]) : "l"(a0), "l"(b2));
                asm("fma.rn.f32x2 %0, %1, %2, %0;" : "+l"(acc[1][j]) : "l"(a1), "l"(b2));
                asm("fma.rn.f32x2 %0, %1, %2, %0;" : "+l"(acc[2][j]) : "l"(a2), "l"(b2));
                asm("fma.rn.f32x2 %0, %1, %2, %0;" : "+l"(acc[3][j]) : "l"(a3), "l"(b2));
            }
        }
        __syncthreads();
    }

    // epilogue: acc + bias, then relu (same op order as R1/R8), row-major out
    int colbase = n0 + wn * 32 + tx * 4;
    float bj[4];
#pragma unroll
    for (int j = 0; j < 4; j++) bj[j] = __ldg(bias + colbase + j);

#pragma unroll
    for (int i = 0; i < 4; i++) {
        int row0 = m0 + wm * 32 + ty * 8 + i * 2;
        float v0[4], v1[4];
#pragma unroll
        for (int j = 0; j < 4; j++) {
            float lo, hi;
            asm("mov.b64 {%0, %1}, %2;" : "=f"(lo), "=f"(hi) : "l"(acc[i][j]));
            lo += bj[j]; hi += bj[j];
            lo = fmaxf(lo, 0.f); hi = fmaxf(hi, 0.f);
            v0[j] = lo; v1[j] = hi;
        }
        *(float4*)(C + (size_t)row0 * Nn + colbase) =
            make_float4(v0[0], v0[1], v0[2], v0[3]);
        *(float4*)(C + (size_t)(row0 + 1) * Nn + colbase) =
            make_float4(v1[0], v1[1], v1[2], v1[3]);
    }
}

// ---------------------------------------------------------------------------
// Heads (identical to R1/R8)
// ---------------------------------------------------------------------------
__global__ void heads_kernel(const float* __restrict__ proposals,
                             const int* __restrict__ imidx,
                             const int* __restrict__ imsizes,
                             const float* __restrict__ cls_w,
                             const float* __restrict__ cls_b,
                             const float* __restrict__ reg_w,
                             const float* __restrict__ reg_b,
                             const float* __restrict__ h2,
                             float* __restrict__ scr_out,
                             float* __restrict__ box_out)
{
    int gt = blockIdx.x * blockDim.x + threadIdx.x;
    int n = gt >> 5;
    int lane = gt & 31;
    if (n >= NPROP) return;

    const float* h = h2 + (size_t)n * CMID;
    float a0 = 0.f, a1 = 0.f, a2 = 0.f, a3 = 0.f, a4 = 0.f, a5 = 0.f;
#pragma unroll 4
    for (int k = lane; k < CMID; k += 32) {
        float hv = h[k];
        a0 += hv * cls_w[k];
        a1 += hv * cls_w[CMID + k];
        a2 += hv * reg_w[4 * CMID + k];
        a3 += hv * reg_w[5 * CMID + k];
        a4 += hv * reg_w[6 * CMID + k];
        a5 += hv * reg_w[7 * CMID + k];
    }
#pragma unroll
    for (int o = 16; o > 0; o >>= 1) {
        a0 += __shfl_down_sync(0xffffffffu, a0, o);
        a1 += __shfl_down_sync(0xffffffffu, a1, o);
        a2 += __shfl_down_sync(0xffffffffu, a2, o);
        a3 += __shfl_down_sync(0xffffffffu, a3, o);
        a4 += __shfl_down_sync(0xffffffffu, a4, o);
        a5 += __shfl_down_sync(0xffffffffu, a5, o);
    }
    if (lane == 0) {
        float l0 = a0 + cls_b[0];
        float l1 = a1 + cls_b[1];
        float m = fmaxf(l0, l1);
        float e0 = expf(l0 - m), e1 = expf(l1 - m);
        float scr = e1 / (e0 + e1);

        float r0 = a2 + reg_b[4];
        float r1 = a3 + reg_b[5];
        float r2 = a4 + reg_b[6];
        float r3 = a5 + reg_b[7];

        float x1 = proposals[n * 4 + 0];
        float y1 = proposals[n * 4 + 1];
        float x2 = proposals[n * 4 + 2];
        float y2 = proposals[n * 4 + 3];
        float w  = x2 - x1, hh = y2 - y1;
        float cx = x1 + 0.5f * w, cy = y1 + 0.5f * hh;
        float dx = r0 / 10.f, dy = r1 / 10.f, dw = r2 / 5.f, dh = r3 / 5.f;
        float pcx = dx * w + cx;
        float pcy = dy * hh + cy;
        float pw = w  * expf(fminf(dw, BBOX_CLAMP));
        float ph = hh * expf(fminf(dh, BBOX_CLAMP));
        int b = imidx[n];
        float szh = (float)imsizes[b * 2 + 0];
        float szw = (float)imsizes[b * 2 + 1];
        float bx1 = fminf(fmaxf(pcx - 0.5f * pw, 0.f), szw);
        float bx2 = fminf(fmaxf(pcx + 0.5f * pw, 0.f), szw);
        float by1 = fminf(fmaxf(pcy - 0.5f * ph, 0.f), szh);
        float by2 = fminf(fmaxf(pcy + 0.5f * ph, 0.f), szh);

        bool keep = (scr > SCORE_THR) && (bx2 - bx1 >= 1.0f) && (by2 - by1 >= 1.0f);
        scr_out[n] = keep ? scr : -1.0f;
        box_out[n * 4 + 0] = bx1;
        box_out[n * 4 + 1] = by1;
        box_out[n * 4 + 2] = bx2;
        box_out[n * 4 + 3] = by2;
    }
}

// ---------------------------------------------------------------------------
// NMS (identical to R1/R8)
// ---------------------------------------------------------------------------
__global__ void nms_kernel(const float* __restrict__ scr_in,
                           const float* __restrict__ box_in,
                           float* __restrict__ out)
{
    int img = blockIdx.x;
    int j = threadIdx.x;
    __shared__ float sscr[PER_IM];
    __shared__ float sred[8];
    __shared__ int   sredi[8];
    __shared__ float sbb[4];
    __shared__ int   sbi;
    __shared__ float sbs;

    int gid = img * PER_IM + j;
    float4 box = ((const float4*)box_in)[gid];
    float area = fmaxf(box.z - box.x, 0.f) * fmaxf(box.w - box.y, 0.f);
    sscr[j] = scr_in[gid];
    __syncthreads();

    for (int t = 0; t < IMTOP; t++) {
        float v = sscr[j];
        int idx = j;
#pragma unroll
        for (int o = 16; o > 0; o >>= 1) {
            float v2 = __shfl_down_sync(0xffffffffu, v, o);
            int   i2 = __shfl_down_sync(0xffffffffu, idx, o);
            if (v2 > v || (v2 == v && i2 < idx)) { v = v2; idx = i2; }
        }
        if ((j & 31) == 0) { sred[j >> 5] = v; sredi[j >> 5] = idx; }
        __syncthreads();
        if (j == 0) {
            float bv = sred[0]; int bi = sredi[0];
#pragma unroll
            for (int w = 1; w < 8; w++) {
                if (sred[w] > bv || (sred[w] == bv && sredi[w] < bi)) {
                    bv = sred[w]; bi = sredi[w];
                }
            }
            sbi = bi; sbs = bv;
        }
        __syncthreads();
        int bi = sbi; float bs = sbs;
        if (j == bi) {
            sbb[0] = box.x; sbb[1] = box.y; sbb[2] = box.z; sbb[3] = box.w;
            int o = img * IMTOP + t;
            out[o * 4 + 0] = box.x;
            out[o * 4 + 1] = box.y;
            out[o * 4 + 2] = box.z;
            out[o * 4 + 3] = box.w;
            float oscr = fmaxf(bs, -1.0f);
            out[3200 + o] = oscr;
            float val = (bs > SCORE_THR) ? 1.0f : 0.0f;
            out[4000 + o] = val;
            out[4800 + o] = val;
        }
        __syncthreads();
        float xx1 = fmaxf(sbb[0], box.x);
        float yy1 = fmaxf(sbb[1], box.y);
        float xx2 = fminf(sbb[2], box.z);
        float yy2 = fminf(sbb[3], box.w);
        float inter = fmaxf(xx2 - xx1, 0.f) * fmaxf(yy2 - yy1, 0.f);
        float barea = fmaxf(sbb[2] - sbb[0], 0.f) * fmaxf(sbb[3] - sbb[1], 0.f);
        float iou = inter / (barea + area - inter + 1e-6f);
        if (iou > IOU_THR) sscr[j] = -INFINITY;
        if (j == bi) sscr[j] = -INFINITY;
        __syncthreads();
    }
}

// ---------------------------------------------------------------------------
// kernel_launch
// ---------------------------------------------------------------------------
extern "C" void kernel_launch(void* const* d_in, const int* in_sizes, int n_in,
                              void* d_out, int out_size)
{
    const float* proposals = (const float*)d_in[0];
    const int*   imidx     = (const int*)  d_in[1];
    const float* f0        = (const float*)d_in[2];
    const float* f1        = (const float*)d_in[3];
    const float* f2        = (const float*)d_in[4];
    const float* f3        = (const float*)d_in[5];
    const int*   imsizes   = (const int*)  d_in[6];
    const float* fc6_w     = (const float*)d_in[7];
    const float* fc6_b     = (const float*)d_in[8];
    const float* fc7_w     = (const float*)d_in[9];
    const float* fc7_b     = (const float*)d_in[10];
    const float* cls_w     = (const float*)d_in[11];
    const float* cls_b     = (const float*)d_in[12];
    const float* reg_w     = (const float*)d_in[13];
    const float* reg_b     = (const float*)d_in[14];
    float* out = (float*)d_out;

    float *pix, *roi, *w6T, *w7T, *h1, *h2, *scr, *box;
    cudaGetSymbolAddress((void**)&pix,  g_pix);
    cudaGetSymbolAddress((void**)&roi,  g_roi);
    cudaGetSymbolAddress((void**)&w6T,  g_w6T);
    cudaGetSymbolAddress((void**)&w7T,  g_w7T);
    cudaGetSymbolAddress((void**)&h1,   g_h1);
    cudaGetSymbolAddress((void**)&h2,   g_h2);
    cudaGetSymbolAddress((void**)&scr,  g_scr);
    cudaGetSymbolAddress((void**)&box,  g_box);

    dim3 tb(32, 8);
    // NCHW -> NHWC per level (X: (256, HW) per image -> Y: (HW, 256))
    ktranspose_s<<<dim3(800, 8, N_IMG), tb>>>(f0, pix + (size_t)0      * CCH,
        CCH, 25600, 25600, CCH, (long long)CCH * 25600, (long long)25600 * CCH);
    ktranspose_s<<<dim3(200, 8, N_IMG), tb>>>(f1, pix + (size_t)204800 * CCH,
        CCH, 6400, 6400, CCH, (long long)CCH * 6400, (long long)6400 * CCH);
    ktranspose_s<<<dim3(50, 8, N_IMG), tb>>>(f2, pix + (size_t)256000 * CCH,
        CCH, 1600, 1600, CCH, (long long)CCH * 1600, (long long)1600 * CCH);
    ktranspose_s<<<dim3(13, 8, N_IMG), tb>>>(f3, pix + (size_t)268800 * CCH,
        CCH, 400, 400, CCH, (long long)CCH * 400, (long long)400 * CCH);

    // fc6_w (m, c*49+p) -> w6T ((p*256+c), m)
    ktranspose_s<<<dim3(2, 32, 256), tb>>>(fc6_w, w6T, CMID, NPTS,
                                           (long long)CIN, (long long)CCH * CMID,
                                           (long long)NPTS, (long long)CMID);
    // fc7_w (m, k) -> w7T (k, m)
    ktranspose_s<<<dim3(32, 32, 1), tb>>>(fc7_w, w7T, CMID, CMID,
                                          (long long)CMID, (long long)CMID,
                                          0, 0);

    roi_align_kernel<<<NPROP, 256>>>(proposals, imidx, pix, roi);

    // FC6: A = roi (n,k) row-major, B = w6T k-major -> h1 row-major
    gemm_an<<<dim3(CMID / GN, NPROP / GM), 256>>>(
        roi, w6T, fc6_b, h1, NPROP, CMID, CIN);
    // FC7: A = h1 (n,k) row-major, B = w7T k-major -> h2 row-major
    gemm_an<<<dim3(CMID / GN, NPROP / GM), 256>>>(
        h1, w7T, fc7_b, h2, NPROP, CMID, CMID);

    heads_kernel<<<NPROP * 32 / 256, 256>>>(proposals, imidx, imsizes,
                                            cls_w, cls_b, reg_w, reg_b,
                                            h2, scr, box);

    nms_kernel<<<N_IMG, PER_IM>>>(scr, box, out);
}

// round 12
// speedup vs baseline: 1.2086x; 1.2086x over previous
#include <cuda_runtime.h>
#include <cuda_bf16.h>
#include <math.h>
#include <stdint.h>

// ---------------------------------------------------------------------------
// Problem constants
// ---------------------------------------------------------------------------
#define N_IMG   8
#define PER_IM  256
#define NPROP   2048
#define CCH     256
#define NPTS    49
#define CIN     12544         // 256*49
#define CMID    1024
#define IMTOP   100
#define SCORE_THR 0.05f
#define IOU_THR   0.5f
#define BBOX_CLAMP 4.135166556742356f

__device__ __constant__ int   c_HS[4]   = {160, 80, 40, 20};
__device__ __constant__ int   c_OFFS[4] = {0, 204800, 256000, 268800};
__device__ __constant__ float c_STR[4]  = {4.f, 8.f, 16.f, 32.f};

#define TOTPX 272000

// ---------------------------------------------------------------------------
// Device scratch
// ---------------------------------------------------------------------------
__device__ __align__(128) float g_pix [TOTPX * CCH];           // NHWC fmaps
__device__ __align__(128) float g_roi [(size_t)NPROP * CIN];   // roi (n, k)
__device__ __align__(128) float g_roiT[(size_t)CIN * NPROP];   // roi (k, n)
__device__ __align__(128) float g_w6T [(size_t)CIN * CMID];    // fc6_w (k, m)
__device__ __align__(128) float g_w7T [(size_t)CMID * CMID];   // fc7_w (k, m)
__device__ __align__(128) float g_h1T [(size_t)CMID * NPROP];  // h1 (k, n)
__device__ __align__(128) float g_h2  [(size_t)NPROP * CMID];
__device__ float g_scr[NPROP];
__device__ float g_box[NPROP * 4];

// ---------------------------------------------------------------------------
// PTX helpers
// ---------------------------------------------------------------------------
__device__ __forceinline__ uint32_t smem_addr_u32(const void* p) {
    uint32_t a;
    asm("{ .reg .u64 t; cvta.to.shared.u64 t, %1; cvt.u32.u64 %0, t; }"
        : "=r"(a) : "l"(p));
    return a;
}
__device__ __forceinline__ void cpa16(uint32_t saddr, const float* g) {
    asm volatile("cp.async.cg.shared.global [%0], [%1], 16;"
                 :: "r"(saddr), "l"(g));
}

// ---------------------------------------------------------------------------
// Dense 32x32 tiled transpose (NCHW->NHWC fmaps) — 1511-winner version
// ---------------------------------------------------------------------------
__global__ void ktranspose(const float* __restrict__ in, float* __restrict__ out,
                           int R, int Cc)
{
    __shared__ float tile[32][33];
    size_t mat = blockIdx.z;
    const float* X = in  + mat * (size_t)R * Cc;
    float*       Y = out + mat * (size_t)R * Cc;
    int j0 = blockIdx.x * 32;
    int i0 = blockIdx.y * 32;
    int tx = threadIdx.x, ty = threadIdx.y;
#pragma unroll
    for (int u = 0; u < 32; u += 8) {
        int i = i0 + ty + u, j = j0 + tx;
        if (i < R && j < Cc) tile[ty + u][tx] = X[(size_t)i * Cc + j];
    }
    __syncthreads();
#pragma unroll
    for (int u = 0; u < 32; u += 8) {
        int j = j0 + ty + u, i = i0 + tx;
        if (j < Cc && i < R) Y[(size_t)j * R + i] = tile[tx][ty + u];
    }
}

// Strided transpose: Y[j*outRS + i] = X[i*inRS + j], per-z base offsets.
__global__ void ktranspose_s(const float* __restrict__ in, float* __restrict__ out,
                             int R, int Cc, long long inRS, long long outRS,
                             long long zIn, long long zOut)
{
    __shared__ float tile[32][33];
    const float* X = in  + (long long)blockIdx.z * zIn;
    float*       Y = out + (long long)blockIdx.z * zOut;
    int j0 = blockIdx.x * 32;
    int i0 = blockIdx.y * 32;
    int tx = threadIdx.x, ty = threadIdx.y;
#pragma unroll
    for (int u = 0; u < 32; u += 8) {
        int i = i0 + ty + u, j = j0 + tx;
        if (i < R && j < Cc) tile[ty + u][tx] = X[(long long)i * inRS + j];
    }
    __syncthreads();
#pragma unroll
    for (int u = 0; u < 32; u += 8) {
        int j = j0 + ty + u, i = i0 + tx;
        if (j < Cc && i < R) Y[(long long)j * outRS + i] = tile[tx][ty + u];
    }
}

// ---------------------------------------------------------------------------
// ROI align (1511-winner version; block per roi, 256 threads = channels)
// ---------------------------------------------------------------------------
__global__ void roi_align_kernel(const float* __restrict__ proposals,
                                 const int* __restrict__ imidx,
                                 const float* __restrict__ pix,
                                 float* __restrict__ roi)
{
    int n = blockIdx.x;
    int c = threadIdx.x;

    __shared__ int   s_idx[NPTS][4];
    __shared__ float s_w[NPTS][4];

    float x1 = proposals[n * 4 + 0];
    float y1 = proposals[n * 4 + 1];
    float x2 = proposals[n * 4 + 2];
    float y2 = proposals[n * 4 + 3];

    float area = fmaxf(x2 - x1, 0.f) * fmaxf(y2 - y1, 0.f);
    float lf = floorf(4.0f + log2f(sqrtf(area) / 224.0f + 1e-8f));
    lf = fminf(fmaxf(lf, 2.0f), 5.0f);
    int lvl = (int)lf - 2;

    int   H  = c_HS[lvl];
    int   W  = H;
    float sc = 1.0f / c_STR[lvl];
    int   b  = imidx[n];
    int   basepx = c_OFFS[lvl] + b * H * W;

    if (threadIdx.x < NPTS) {
        int p = threadIdx.x;
        int i = p / 7, j = p % 7;
        float stepx = (x2 - x1) * sc / 7.0f;
        float stepy = (y2 - y1) * sc / 7.0f;
        float gx = x1 * sc + ((float)j + 0.5f) * stepx;
        float gy = y1 * sc + ((float)i + 0.5f) * stepy;
        float x = fminf(fmaxf(gx, 0.f), (float)W - 1.0f);
        float y = fminf(fmaxf(gy, 0.f), (float)H - 1.0f);
        float x0f = floorf(x), y0f = floorf(y);
        int x0i = (int)x0f, y0i = (int)y0f;
        int x1i = min(x0i + 1, W - 1);
        int y1i = min(y0i + 1, H - 1);
        float fx = x - x0f, fy = y - y0f;
        s_idx[p][0] = basepx + y0i * W + x0i;
        s_idx[p][1] = basepx + y0i * W + x1i;
        s_idx[p][2] = basepx + y1i * W + x0i;
        s_idx[p][3] = basepx + y1i * W + x1i;
        s_w[p][0] = (1.f - fy) * (1.f - fx);
        s_w[p][1] = (1.f - fy) * fx;
        s_w[p][2] = fy * (1.f - fx);
        s_w[p][3] = fy * fx;
    }
    __syncthreads();

    float* out = roi + (size_t)n * CIN;
#pragma unroll 1
    for (int p = 0; p < NPTS; p++) {
        float v = s_w[p][0] * pix[(size_t)s_idx[p][0] * CCH + c]
                + s_w[p][1] * pix[(size_t)s_idx[p][1] * CCH + c]
                + s_w[p][2] * pix[(size_t)s_idx[p][2] * CCH + c]
                + s_w[p][3] * pix[(size_t)s_idx[p][3] * CCH + c];
        out[p * CCH + c] = v;
    }
}

// ---------------------------------------------------------------------------
// k-major fp32 GEMM, bitwise-identical numerics to the 1511 run:
//   per element: single fp32 accumulator, fma.rn over ascending k,
//   then acc + bias, then fmaxf.
// Tile/schedule identical to the 1511 winner: 128m x 64n x 16k, 256 thr,
// 8 warps (4m x 2n of 32x32), thread 8m x 4n, double-buffered, 2 CTAs/SM.
// ONLY CHANGE: A tile moves off the LDGSTS pipe — LDG.128 register prefetch
// (issued one chunk ahead, latency hidden behind compute) + conflict-free
// STS.128. B stays cp.async. LDGSTS ops/round drop 3072 -> 1024 cyc.
// TRANSOUT=1: write C transposed (Nn x M, k-major for the next layer).
// ---------------------------------------------------------------------------
#define GM 128
#define GN 64
#define GK 16

template <int TRANSOUT>
__global__ __launch_bounds__(256, 2)
void gemm_kmaj(const float* __restrict__ AT, const float* __restrict__ BT,
               const float* __restrict__ bias, float* __restrict__ C,
               int M, int Nn, int K)
{
    __shared__ float As[2][GK][GM];
    __shared__ float Bs[2][GK][GN];

    const int tid = threadIdx.x;
    const int wid = tid >> 5;
    const int lane = tid & 31;
    const int wm = wid & 3;           // 4 m-slots of 32
    const int wn = wid >> 2;          // 2 n-slots of 32
    const int ty = lane >> 3;         // 4 m-subslots of 8
    const int tx = lane & 7;          // 8 n-subslots of 4
    const int m0 = blockIdx.y * GM;
    const int n0 = blockIdx.x * GN;

    // A-load mapping: 512 float4 per chunk, 2 per thread
    const int akr0 = tid >> 5;            // k row for p=0 (0..7)
    const int acm  = (tid & 31) * 4;      // m column

    // B cp.async mapping: 256 float4 per chunk, 1 per thread
    const int bkr = tid >> 4;
    const int bcn = (tid & 15) * 4;

    // acc[i][j]: packed fp32 pair = rows (ty*8+2i, ty*8+2i+1), col j
    unsigned long long acc[4][4];
#pragma unroll
    for (int i = 0; i < 4; i++)
#pragma unroll
        for (int j = 0; j < 4; j++) acc[i][j] = 0ull;

    const int NCH = K / GK;

    float4 va[2];

    // prologue: chunk 0
    {
        va[0] = *(const float4*)(AT + (size_t)(akr0)     * M + m0 + acm);
        va[1] = *(const float4*)(AT + (size_t)(akr0 + 8) * M + m0 + acm);
        cpa16(smem_addr_u32(&Bs[0][bkr][bcn]), BT + (size_t)bkr * Nn + n0 + bcn);
        asm volatile("cp.async.commit_group;");
        *(float4*)&As[0][akr0][acm]     = va[0];
        *(float4*)&As[0][akr0 + 8][acm] = va[1];
        asm volatile("cp.async.wait_group 0;");
    }
    __syncthreads();

    for (int ch = 0; ch < NCH; ch++) {
        int s = ch & 1;
        if (ch + 1 < NCH) {
            int kc = (ch + 1) * GK;
            // B for ch+1: async, lands during this chunk's compute
            cpa16(smem_addr_u32(&Bs[s ^ 1][bkr][bcn]),
                  BT + (size_t)(kc + bkr) * Nn + n0 + bcn);
            asm volatile("cp.async.commit_group;");
            // A for ch+1: register prefetch, latency hidden behind compute
            va[0] = *(const float4*)(AT + (size_t)(kc + akr0)     * M + m0 + acm);
            va[1] = *(const float4*)(AT + (size_t)(kc + akr0 + 8) * M + m0 + acm);
        }

#pragma unroll
        for (int kk = 0; kk < GK; kk++) {
            const unsigned long long* ap =
                (const unsigned long long*)&As[s][kk][wm * 32 + ty * 8];
            unsigned long long a0 = ap[0], a1 = ap[1], a2 = ap[2], a3 = ap[3];
            const float4 bv = *(const float4*)&Bs[s][kk][wn * 32 + tx * 4];
            const float* b = &bv.x;
#pragma unroll
            for (int j = 0; j < 4; j++) {
                unsigned long long b2;
                asm("mov.b64 %0, {%1, %1};" : "=l"(b2) : "f"(b[j]));
                asm("fma.rn.f32x2 %0, %1, %2, %0;" : "+l"(acc[0][j]) : "l"(a0), "l"(b2));
                asm("fma.rn.f32x2 %0, %1, %2, %0;" : "+l"(acc[1][j]) : "l"(a1), "l"(b2));
                asm("fma.rn.f32x2 %0, %1, %2, %0;" : "+l"(acc[2][j]) : "l"(a2), "l"(b2));
                asm("fma.rn.f32x2 %0, %1, %2, %0;" : "+l"(acc[3][j]) : "l"(a3), "l"(b2));
            }
        }

        if (ch + 1 < NCH) {
            *(float4*)&As[s ^ 1][akr0][acm]     = va[0];
            *(float4*)&As[s ^ 1][akr0 + 8][acm] = va[1];
            asm volatile("cp.async.wait_group 0;");
        }
        __syncthreads();
    }

    // epilogue: acc + bias, then relu (same op order as the 1511 run)
    int colbase = n0 + wn * 32 + tx * 4;
    float bj[4];
#pragma unroll
    for (int j = 0; j < 4; j++) bj[j] = __ldg(bias + colbase + j);

#pragma unroll
    for (int i = 0; i < 4; i++) {
        int row0 = m0 + wm * 32 + ty * 8 + i * 2;
        float v0[4], v1[4];
#pragma unroll
        for (int j = 0; j < 4; j++) {
            float lo, hi;
            asm("mov.b64 {%0, %1}, %2;" : "=f"(lo), "=f"(hi) : "l"(acc[i][j]));
            lo += bj[j]; hi += bj[j];
            lo = fmaxf(lo, 0.f); hi = fmaxf(hi, 0.f);
            v0[j] = lo; v1[j] = hi;
        }
        if (TRANSOUT) {
#pragma unroll
            for (int j = 0; j < 4; j++) {
                *(float2*)(C + (size_t)(colbase + j) * M + row0) =
                    make_float2(v0[j], v1[j]);
            }
        } else {
            *(float4*)(C + (size_t)row0 * Nn + colbase) =
                make_float4(v0[0], v0[1], v0[2], v0[3]);
            *(float4*)(C + (size_t)(row0 + 1) * Nn + colbase) =
                make_float4(v1[0], v1[1], v1[2], v1[3]);
        }
    }
}

// ---------------------------------------------------------------------------
// Heads (identical to 1511 run)
// ---------------------------------------------------------------------------
__global__ void heads_kernel(const float* __restrict__ proposals,
                             const int* __restrict__ imidx,
                             const int* __restrict__ imsizes,
                             const float* __restrict__ cls_w,
                             const float* __restrict__ cls_b,
                             const float* __restrict__ reg_w,
                             const float* __restrict__ reg_b,
                             const float* __restrict__ h2,
                             float* __restrict__ scr_out,
                             float* __restrict__ box_out)
{
    int gt = blockIdx.x * blockDim.x + threadIdx.x;
    int n = gt >> 5;
    int lane = gt & 31;
    if (n >= NPROP) return;

    const float* h = h2 + (size_t)n * CMID;
    float a0 = 0.f, a1 = 0.f, a2 = 0.f, a3 = 0.f, a4 = 0.f, a5 = 0.f;
#pragma unroll 4
    for (int k = lane; k < CMID; k += 32) {
        float hv = h[k];
        a0 += hv * cls_w[k];
        a1 += hv * cls_w[CMID + k];
        a2 += hv * reg_w[4 * CMID + k];
        a3 += hv * reg_w[5 * CMID + k];
        a4 += hv * reg_w[6 * CMID + k];
        a5 += hv * reg_w[7 * CMID + k];
    }
#pragma unroll
    for (int o = 16; o > 0; o >>= 1) {
        a0 += __shfl_down_sync(0xffffffffu, a0, o);
        a1 += __shfl_down_sync(0xffffffffu, a1, o);
        a2 += __shfl_down_sync(0xffffffffu, a2, o);
        a3 += __shfl_down_sync(0xffffffffu, a3, o);
        a4 += __shfl_down_sync(0xffffffffu, a4, o);
        a5 += __shfl_down_sync(0xffffffffu, a5, o);
    }
    if (lane == 0) {
        float l0 = a0 + cls_b[0];
        float l1 = a1 + cls_b[1];
        float m = fmaxf(l0, l1);
        float e0 = expf(l0 - m), e1 = expf(l1 - m);
        float scr = e1 / (e0 + e1);

        float r0 = a2 + reg_b[4];
        float r1 = a3 + reg_b[5];
        float r2 = a4 + reg_b[6];
        float r3 = a5 + reg_b[7];

        float x1 = proposals[n * 4 + 0];
        float y1 = proposals[n * 4 + 1];
        float x2 = proposals[n * 4 + 2];
        float y2 = proposals[n * 4 + 3];
        float w  = x2 - x1, hh = y2 - y1;
        float cx = x1 + 0.5f * w, cy = y1 + 0.5f * hh;
        float dx = r0 / 10.f, dy = r1 / 10.f, dw = r2 / 5.f, dh = r3 / 5.f;
        float pcx = dx * w + cx;
        float pcy = dy * hh + cy;
        float pw = w  * expf(fminf(dw, BBOX_CLAMP));
        float ph = hh * expf(fminf(dh, BBOX_CLAMP));
        int b = imidx[n];
        float szh = (float)imsizes[b * 2 + 0];
        float szw = (float)imsizes[b * 2 + 1];
        float bx1 = fminf(fmaxf(pcx - 0.5f * pw, 0.f), szw);
        float bx2 = fminf(fmaxf(pcx + 0.5f * pw, 0.f), szw);
        float by1 = fminf(fmaxf(pcy - 0.5f * ph, 0.f), szh);
        float by2 = fminf(fmaxf(pcy + 0.5f * ph, 0.f), szh);

        bool keep = (scr > SCORE_THR) && (bx2 - bx1 >= 1.0f) && (by2 - by1 >= 1.0f);
        scr_out[n] = keep ? scr : -1.0f;
        box_out[n * 4 + 0] = bx1;
        box_out[n * 4 + 1] = by1;
        box_out[n * 4 + 2] = bx2;
        box_out[n * 4 + 3] = by2;
    }
}

// ---------------------------------------------------------------------------
// NMS (identical to 1511 run)
// ---------------------------------------------------------------------------
__global__ void nms_kernel(const float* __restrict__ scr_in,
                           const float* __restrict__ box_in,
                           float* __restrict__ out)
{
    int img = blockIdx.x;
    int j = threadIdx.x;
    __shared__ float sscr[PER_IM];
    __shared__ float sred[8];
    __shared__ int   sredi[8];
    __shared__ float sbb[4];
    __shared__ int   sbi;
    __shared__ float sbs;

    int gid = img * PER_IM + j;
    float4 box = ((const float4*)box_in)[gid];
    float area = fmaxf(box.z - box.x, 0.f) * fmaxf(box.w - box.y, 0.f);
    sscr[j] = scr_in[gid];
    __syncthreads();

    for (int t = 0; t < IMTOP; t++) {
        float v = sscr[j];
        int idx = j;
#pragma unroll
        for (int o = 16; o > 0; o >>= 1) {
            float v2 = __shfl_down_sync(0xffffffffu, v, o);
            int   i2 = __shfl_down_sync(0xffffffffu, idx, o);
            if (v2 > v || (v2 == v && i2 < idx)) { v = v2; idx = i2; }
        }
        if ((j & 31) == 0) { sred[j >> 5] = v; sredi[j >> 5] = idx; }
        __syncthreads();
        if (j == 0) {
            float bv = sred[0]; int bi = sredi[0];
#pragma unroll
            for (int w = 1; w < 8; w++) {
                if (sred[w] > bv || (sred[w] == bv && sredi[w] < bi)) {
                    bv = sred[w]; bi = sredi[w];
                }
            }
            sbi = bi; sbs = bv;
        }
        __syncthreads();
        int bi = sbi; float bs = sbs;
        if (j == bi) {
            sbb[0] = box.x; sbb[1] = box.y; sbb[2] = box.z; sbb[3] = box.w;
            int o = img * IMTOP + t;
            out[o * 4 + 0] = box.x;
            out[o * 4 + 1] = box.y;
            out[o * 4 + 2] = box.z;
            out[o * 4 + 3] = box.w;
            float oscr = fmaxf(bs, -1.0f);
            out[3200 + o] = oscr;
            float val = (bs > SCORE_THR) ? 1.0f : 0.0f;
            out[4000 + o] = val;
            out[4800 + o] = val;
        }
        __syncthreads();
        float xx1 = fmaxf(sbb[0], box.x);
        float yy1 = fmaxf(sbb[1], box.y);
        float xx2 = fminf(sbb[2], box.z);
        float yy2 = fminf(sbb[3], box.w);
        float inter = fmaxf(xx2 - xx1, 0.f) * fmaxf(yy2 - yy1, 0.f);
        float barea = fmaxf(sbb[2] - sbb[0], 0.f) * fmaxf(sbb[3] - sbb[1], 0.f);
        float iou = inter / (barea + area - inter + 1e-6f);
        if (iou > IOU_THR) sscr[j] = -INFINITY;
        if (j == bi) sscr[j] = -INFINITY;
        __syncthreads();
    }
}

// ---------------------------------------------------------------------------
// kernel_launch — identical to the 1511 run
// ---------------------------------------------------------------------------
extern "C" void kernel_launch(void* const* d_in, const int* in_sizes, int n_in,
                              void* d_out, int out_size)
{
    const float* proposals = (const float*)d_in[0];
    const int*   imidx     = (const int*)  d_in[1];
    const float* f0        = (const float*)d_in[2];
    const float* f1        = (const float*)d_in[3];
    const float* f2        = (const float*)d_in[4];
    const float* f3        = (const float*)d_in[5];
    const int*   imsizes   = (const int*)  d_in[6];
    const float* fc6_w     = (const float*)d_in[7];
    const float* fc6_b     = (const float*)d_in[8];
    const float* fc7_w     = (const float*)d_in[9];
    const float* fc7_b     = (const float*)d_in[10];
    const float* cls_w     = (const float*)d_in[11];
    const float* cls_b     = (const float*)d_in[12];
    const float* reg_w     = (const float*)d_in[13];
    const float* reg_b     = (const float*)d_in[14];
    float* out = (float*)d_out;

    float *pix, *roi, *roiT, *w6T, *w7T, *h1T, *h2, *scr, *box;
    cudaGetSymbolAddress((void**)&pix,  g_pix);
    cudaGetSymbolAddress((void**)&roi,  g_roi);
    cudaGetSymbolAddress((void**)&roiT, g_roiT);
    cudaGetSymbolAddress((void**)&w6T,  g_w6T);
    cudaGetSymbolAddress((void**)&w7T,  g_w7T);
    cudaGetSymbolAddress((void**)&h1T,  g_h1T);
    cudaGetSymbolAddress((void**)&h2,   g_h2);
    cudaGetSymbolAddress((void**)&scr,  g_scr);
    cudaGetSymbolAddress((void**)&box,  g_box);

    dim3 tb(32, 8);
    // NCHW -> NHWC per level
    ktranspose<<<dim3(800, 8, N_IMG), tb>>>(f0, pix + (size_t)0      * CCH, CCH, 25600);
    ktranspose<<<dim3(200, 8, N_IMG), tb>>>(f1, pix + (size_t)204800 * CCH, CCH, 6400);
    ktranspose<<<dim3(50,  8, N_IMG), tb>>>(f2, pix + (size_t)256000 * CCH, CCH, 1600);
    ktranspose<<<dim3(13,  8, N_IMG), tb>>>(f3, pix + (size_t)268800 * CCH, CCH, 400);

    // fc6_w (m, c*49+p) -> w6T ((p*256+c), m)
    ktranspose_s<<<dim3(2, 32, 256), tb>>>(fc6_w, w6T, CMID, NPTS,
                                           (long long)CIN, (long long)CCH * CMID,
                                           (long long)NPTS, (long long)CMID);
    // fc7_w (m, k) -> w7T (k, m)
    ktranspose_s<<<dim3(32, 32, 1), tb>>>(fc7_w, w7T, CMID, CMID,
                                          (long long)CMID, (long long)CMID,
                                          0, 0);

    roi_align_kernel<<<NPROP, 256>>>(proposals, imidx, pix, roi);
    // roi (n, k) -> roiT (k, n)
    ktranspose_s<<<dim3(392, 64, 1), tb>>>(roi, roiT, NPROP, CIN,
                                           (long long)CIN, (long long)NPROP,
                                           0, 0);

    // FC6: (2048 x 1024 x 12544), writes h1T (k-major for FC7)
    gemm_kmaj<1><<<dim3(CMID / GN, NPROP / GM), 256>>>(
        roiT, w6T, fc6_b, h1T, NPROP, CMID, CIN);
    // FC7: (2048 x 1024 x 1024), writes h2 row-major
    gemm_kmaj<0><<<dim3(CMID / GN, NPROP / GM), 256>>>(
        h1T, w7T, fc7_b, h2, NPROP, CMID, CMID);

    heads_kernel<<<NPROP * 32 / 256, 256>>>(proposals, imidx, imsizes,
                                            cls_w, cls_b, reg_w, reg_b,
                                            h2, scr, box);

    nms_kernel<<<N_IMG, PER_IM>>>(scr, box, out);
}